// round 11
// baseline (speedup 1.0000x reference)
#include <cuda_runtime.h>
#include <cuda_bf16.h>

// NaiveVisCache R10: two-phase, u16-packed ratio table, edge-tuned.
//  Phase 1: pack (n | d<<8) u16 -> 25MB table, evict_last. 8 entries/thread
//           (2x int4 loads per table, one 16B store) for DRAM efficiency.
//  Phase 2: 4 rays/thread, launch_bounds(256,8) -> 32 regs, 64 warps (100%
//           occ). Phase 2 is AT the L1tex wavefront floor: 4.19M divergent
//           gathers x 2.07 cyc/wf / 148 SM ~= 33.5us (matches R9's 33.9
//           measured) -- occupancy just needs to keep the queue fed.
// Numerics bit-exact (rel_err 0.0 since R4): face via rcp.rn+mul, output via
// fdiv_rn on the exact small-int n,d recovered from the packed u16.

#define VGRID 128
#define TABLE_N (VGRID * VGRID * VGRID * 6)   // 12,582,912 entries

__device__ unsigned short g_pack[TABLE_N];    // 25.2MB static scratch

__device__ __forceinline__ unsigned long long evict_last_policy() {
    unsigned long long pol;
    asm("createpolicy.fractional.L2::evict_last.b64 %0, 1.0;" : "=l"(pol));
    return pol;
}

// ---------------- Phase 1: pack tables (8 entries/thread) ----------------
__device__ __forceinline__ unsigned int pack2(int n0, int d0, int n1, int d1) {
    return (unsigned int)(n0 | (d0 << 8)) | ((unsigned int)(n1 | (d1 << 8)) << 16);
}

__global__ void __launch_bounds__(256, 8)
pack_kernel(const int4* __restrict__ numer4,
            const int4* __restrict__ denom4,
            int nvec8) {
    int t = blockIdx.x * blockDim.x + threadIdx.x;
    if (t >= nvec8) return;
    unsigned long long pol = evict_last_policy();

    int4 na = __ldcs(numer4 + 2 * t + 0);
    int4 nb = __ldcs(numer4 + 2 * t + 1);
    int4 da = __ldcs(denom4 + 2 * t + 0);
    int4 db = __ldcs(denom4 + 2 * t + 1);

    unsigned int w0 = pack2(na.x, da.x, na.y, da.y);
    unsigned int w1 = pack2(na.z, da.z, na.w, da.w);
    unsigned int w2 = pack2(nb.x, db.x, nb.y, db.y);
    unsigned int w3 = pack2(nb.z, db.z, nb.w, db.w);

    asm volatile("st.global.L2::cache_hint.v4.b32 [%0], {%1,%2,%3,%4}, %5;"
                 :: "l"(g_pack + 8 * (size_t)t),
                    "r"(w0), "r"(w1), "r"(w2), "r"(w3), "l"(pol));
}

// ---------------- index math (bit-exact vs reference) ----------------
__device__ __forceinline__ int coord_clip(float o) {
    float t = (o * 0.5f + 0.5f) * (float)(VGRID - 1);
    t = fminf(fmaxf(t, 0.0f), (float)(VGRID - 1));
    return (int)t;
}

__device__ __forceinline__ int ray_index(float o0, float o1, float o2,
                                         float d0, float d1, float d2) {
    float inf = fmaxf(fabsf(d0), fmaxf(fabsf(d1), fabsf(d2)));
    // Reference: sqdirs = viewdirs * RN(1/inf_norm) (verified bit-exact, R4).
    float rinf = __frcp_rn(inf);
    float sa = d0 * rinf;
    float sb = d1 * rinf;
    float sc = d2 * rinf;
    int f = 0;
    if (sa >=  1.0f) f = 0;
    if (sa <= -1.0f) f = 1;
    if (sb >=  1.0f) f = 2;
    if (sb <= -1.0f) f = 3;
    if (sc >=  1.0f) f = 4;
    if (sc <= -1.0f) f = 5;
    int i = coord_clip(o0);
    int j = coord_clip(o1);
    int k = coord_clip(o2);
    return (((i * VGRID + j) * VGRID + k) * 6) + f;
}

__device__ __forceinline__ unsigned int gather_pack(int idx,
                                                    unsigned long long pol) {
    unsigned int v;
    asm volatile("ld.global.L2::cache_hint.u16 %0, [%1], %2;"
                 : "=r"(v) : "l"(g_pack + idx), "l"(pol));
    return v;
}

__device__ __forceinline__ float decode_div(unsigned int p) {
    float n = (float)(int)(p & 0xFFu);
    float d = (float)(int)(p >> 8);
    return __fdiv_rn(n, d);   // same instruction/values as reference path
}

// ---------------- Phase 2: gather, 4 rays/thread ----------------
__global__ void __launch_bounds__(256, 8)
vis_cache_kernel(const float4* __restrict__ o4,
                 const float4* __restrict__ v4,
                 float4*       __restrict__ out,
                 int nquads) {
    int t = blockIdx.x * blockDim.x + threadIdx.x;
    if (t >= nquads) return;
    unsigned long long pol = evict_last_policy();

    float4 oa = __ldcs(o4 + 3 * t + 0);
    float4 ob = __ldcs(o4 + 3 * t + 1);
    float4 oc = __ldcs(o4 + 3 * t + 2);
    float4 va = __ldcs(v4 + 3 * t + 0);
    float4 vb = __ldcs(v4 + 3 * t + 1);
    float4 vc = __ldcs(v4 + 3 * t + 2);

    int idx0 = ray_index(oa.x, oa.y, oa.z, va.x, va.y, va.z);
    int idx1 = ray_index(oa.w, ob.x, ob.y, va.w, vb.x, vb.y);
    int idx2 = ray_index(ob.z, ob.w, oc.x, vb.z, vb.w, vc.x);
    int idx3 = ray_index(oc.y, oc.z, oc.w, vc.y, vc.z, vc.w);

    // Batched gathers (MLP=4) from the L2-resident 25MB table.
    unsigned int p0 = gather_pack(idx0, pol);
    unsigned int p1 = gather_pack(idx1, pol);
    unsigned int p2 = gather_pack(idx2, pol);
    unsigned int p3 = gather_pack(idx3, pol);

    float4 r;
    r.x = decode_div(p0);
    r.y = decode_div(p1);
    r.z = decode_div(p2);
    r.w = decode_div(p3);
    __stcs(out + t, r);
}

__global__ void __launch_bounds__(256)
vis_cache_tail(const float* __restrict__ origins,
               const float* __restrict__ dirs,
               float*       __restrict__ out,
               int start, int nrays) {
    int r = start + blockIdx.x * blockDim.x + threadIdx.x;
    if (r >= nrays) return;
    int idx = ray_index(origins[3 * r], origins[3 * r + 1], origins[3 * r + 2],
                        dirs[3 * r],    dirs[3 * r + 1],    dirs[3 * r + 2]);
    unsigned int p = g_pack[idx];
    out[r] = __fdiv_rn((float)(int)(p & 0xFFu), (float)(int)(p >> 8));
}

extern "C" void kernel_launch(void* const* d_in, const int* in_sizes, int n_in,
                              void* d_out, int out_size) {
    const float* origins = (const float*)d_in[0];  // [B,3] f32
    const float* dirs    = (const float*)d_in[1];  // [B,3] f32
    const int*   numer   = (const int*)d_in[2];    // [128,128,128,6] i32
    const int*   denom   = (const int*)d_in[3];    // [128,128,128,6] i32
    float* out = (float*)d_out;

    // Phase 1: pack, 8 entries/thread (TABLE_N divisible by 8)
    {
        int nvec8 = TABLE_N / 8;
        pack_kernel<<<(nvec8 + 255) / 256, 256>>>(
            (const int4*)numer, (const int4*)denom, nvec8);
    }

    // Phase 2: gather, 4 rays/thread
    int nrays  = in_sizes[0] / 3;
    int nquads = nrays >> 2;
    if (nquads > 0) {
        vis_cache_kernel<<<(nquads + 255) / 256, 256>>>(
            (const float4*)origins, (const float4*)dirs, (float4*)out, nquads);
    }
    int tail_start = nquads << 2;
    int tail = nrays - tail_start;
    if (tail > 0) {
        vis_cache_tail<<<(tail + 255) / 256, 256>>>(
            origins, dirs, out, tail_start, nrays);
    }
}

// round 12
// speedup vs baseline: 1.0268x; 1.0268x over previous
#include <cuda_runtime.h>
#include <cuda_bf16.h>

// NaiveVisCache R11: R9 config restored (measured best) + .nc gather path.
//  Phase 1: pack (n | d<<8) u16 -> 25MB table, evict_last, 4 entries/thread
//           (R10's 8/thread measured slightly worse -> reverted).
//  Phase 2: 4 rays/thread, launch_bounds(256,8) (32 regs, ~86% occ).
//           Phase 2 sits AT the L1tex wavefront floor: 4.19M divergent
//           gathers x 2.07 cyc/wf / 148 SM ~= 33.5us (measured 33.9-34.2
//           across R9/R10). Gathers now use ld.global.nc (read-only) to
//           shave L1tex path overhead; table is never written in-kernel.
// Numerics bit-exact (rel_err 0.0 since R4): face via rcp.rn+mul, output via
// fdiv_rn on the exact small-int n,d recovered from the packed u16.

#define VGRID 128
#define TABLE_N (VGRID * VGRID * VGRID * 6)   // 12,582,912 entries

__device__ unsigned short g_pack[TABLE_N];    // 25.2MB static scratch

__device__ __forceinline__ unsigned long long evict_last_policy() {
    unsigned long long pol;
    asm("createpolicy.fractional.L2::evict_last.b64 %0, 1.0;" : "=l"(pol));
    return pol;
}

// ---------------- Phase 1: pack tables (4 entries/thread) ----------------
__global__ void __launch_bounds__(256)
pack_kernel(const int4* __restrict__ numer4,
            const int4* __restrict__ denom4,
            int nvec) {
    int t = blockIdx.x * blockDim.x + threadIdx.x;
    if (t >= nvec) return;
    unsigned long long pol = evict_last_policy();

    int4 n = __ldcs(numer4 + t);   // touch-once streams
    int4 d = __ldcs(denom4 + t);
    unsigned int lo = (unsigned int)(n.x | (d.x << 8)) |
                      ((unsigned int)(n.y | (d.y << 8)) << 16);
    unsigned int hi = (unsigned int)(n.z | (d.z << 8)) |
                      ((unsigned int)(n.w | (d.w << 8)) << 16);
    unsigned long long v = (unsigned long long)lo | ((unsigned long long)hi << 32);
    asm volatile("st.global.L2::cache_hint.b64 [%0], %1, %2;"
                 :: "l"((unsigned long long*)(g_pack + 4 * (size_t)t)),
                    "l"(v), "l"(pol));
}

// ---------------- index math (bit-exact vs reference) ----------------
__device__ __forceinline__ int coord_clip(float o) {
    float t = (o * 0.5f + 0.5f) * (float)(VGRID - 1);
    t = fminf(fmaxf(t, 0.0f), (float)(VGRID - 1));
    return (int)t;
}

__device__ __forceinline__ int ray_index(float o0, float o1, float o2,
                                         float d0, float d1, float d2) {
    float inf = fmaxf(fabsf(d0), fmaxf(fabsf(d1), fabsf(d2)));
    // Reference: sqdirs = viewdirs * RN(1/inf_norm) (verified bit-exact, R4).
    float rinf = __frcp_rn(inf);
    float sa = d0 * rinf;
    float sb = d1 * rinf;
    float sc = d2 * rinf;
    int f = 0;
    if (sa >=  1.0f) f = 0;
    if (sa <= -1.0f) f = 1;
    if (sb >=  1.0f) f = 2;
    if (sb <= -1.0f) f = 3;
    if (sc >=  1.0f) f = 4;
    if (sc <= -1.0f) f = 5;
    int i = coord_clip(o0);
    int j = coord_clip(o1);
    int k = coord_clip(o2);
    return (((i * VGRID + j) * VGRID + k) * 6) + f;
}

__device__ __forceinline__ unsigned int gather_pack(int idx,
                                                    unsigned long long pol) {
    unsigned int v;
    asm volatile("ld.global.nc.L2::cache_hint.u16 %0, [%1], %2;"
                 : "=r"(v) : "l"(g_pack + idx), "l"(pol));
    return v;
}

__device__ __forceinline__ float decode_div(unsigned int p) {
    float n = (float)(int)(p & 0xFFu);
    float d = (float)(int)(p >> 8);
    return __fdiv_rn(n, d);   // same instruction/values as reference path
}

// ---------------- Phase 2: gather, 4 rays/thread ----------------
__global__ void __launch_bounds__(256, 8)
vis_cache_kernel(const float4* __restrict__ o4,
                 const float4* __restrict__ v4,
                 float4*       __restrict__ out,
                 int nquads) {
    int t = blockIdx.x * blockDim.x + threadIdx.x;
    if (t >= nquads) return;
    unsigned long long pol = evict_last_policy();

    float4 oa = __ldcs(o4 + 3 * t + 0);
    float4 ob = __ldcs(o4 + 3 * t + 1);
    float4 oc = __ldcs(o4 + 3 * t + 2);
    float4 va = __ldcs(v4 + 3 * t + 0);
    float4 vb = __ldcs(v4 + 3 * t + 1);
    float4 vc = __ldcs(v4 + 3 * t + 2);

    int idx0 = ray_index(oa.x, oa.y, oa.z, va.x, va.y, va.z);
    int idx1 = ray_index(oa.w, ob.x, ob.y, va.w, vb.x, vb.y);
    int idx2 = ray_index(ob.z, ob.w, oc.x, vb.z, vb.w, vc.x);
    int idx3 = ray_index(oc.y, oc.z, oc.w, vc.y, vc.z, vc.w);

    // Batched gathers (MLP=4) from the L2-resident 25MB table.
    unsigned int p0 = gather_pack(idx0, pol);
    unsigned int p1 = gather_pack(idx1, pol);
    unsigned int p2 = gather_pack(idx2, pol);
    unsigned int p3 = gather_pack(idx3, pol);

    float4 r;
    r.x = decode_div(p0);
    r.y = decode_div(p1);
    r.z = decode_div(p2);
    r.w = decode_div(p3);
    __stcs(out + t, r);
}

__global__ void __launch_bounds__(256)
vis_cache_tail(const float* __restrict__ origins,
               const float* __restrict__ dirs,
               float*       __restrict__ out,
               int start, int nrays) {
    int r = start + blockIdx.x * blockDim.x + threadIdx.x;
    if (r >= nrays) return;
    int idx = ray_index(origins[3 * r], origins[3 * r + 1], origins[3 * r + 2],
                        dirs[3 * r],    dirs[3 * r + 1],    dirs[3 * r + 2]);
    unsigned int p = g_pack[idx];
    out[r] = __fdiv_rn((float)(int)(p & 0xFFu), (float)(int)(p >> 8));
}

extern "C" void kernel_launch(void* const* d_in, const int* in_sizes, int n_in,
                              void* d_out, int out_size) {
    const float* origins = (const float*)d_in[0];  // [B,3] f32
    const float* dirs    = (const float*)d_in[1];  // [B,3] f32
    const int*   numer   = (const int*)d_in[2];    // [128,128,128,6] i32
    const int*   denom   = (const int*)d_in[3];    // [128,128,128,6] i32
    float* out = (float*)d_out;

    // Phase 1: pack (TABLE_N divisible by 4)
    {
        int nvec = TABLE_N / 4;
        pack_kernel<<<(nvec + 255) / 256, 256>>>(
            (const int4*)numer, (const int4*)denom, nvec);
    }

    // Phase 2: gather, 4 rays/thread
    int nrays  = in_sizes[0] / 3;
    int nquads = nrays >> 2;
    if (nquads > 0) {
        vis_cache_kernel<<<(nquads + 255) / 256, 256>>>(
            (const float4*)origins, (const float4*)dirs, (float4*)out, nquads);
    }
    int tail_start = nquads << 2;
    int tail = nrays - tail_start;
    if (tail > 0) {
        vis_cache_tail<<<(tail + 255) / 256, 256>>>(
            origins, dirs, out, tail_start, nrays);
    }
}